// round 10
// baseline (speedup 1.0000x reference)
#include <cuda_runtime.h>
#include <cuda_bf16.h>
#include <math.h>
#include <stdint.h>

// Problem constants
#define BATCH 32
#define TT 64
#define SS 64
#define VV 32000
#define EE 512
#define HH 512
#define NCTA 96

// ---------------- device scratch ----------------
__device__ float g_embF[2048 * 512];             // embedded fp32, row = t*32+b
__device__ float g_encproj[2048 * 512];          // enc @ W_a, row = b*64+s
__device__ float g_encIHC[2048 * 2048];          // enc @ Wih0[:,512:]^T, row = b*64+s
__device__ float g_h[2 * BATCH * HH];            // fp32 state
__device__ float g_c[2 * BATCH * HH];
__device__ float g_feat[TT * BATCH * 1024];      // [t][b][ h1 | ctx ]
__device__ float g_embpre[TT * BATCH * 2048];    // emb @ Wih0[:, :512]^T
__device__ float g_g0ctx[BATCH * 2048];          // attn @ encIHC
__device__ unsigned g_barcnt;
// packed 3-way tf32 weights: HM = uint4{H0,H1,M0,M1}, L = uint2{L0,L1}
// index (nt8*64 + ki8)*32 + lane
__device__ uint4 g_WaT_hm[64 * 64 * 32];
__device__ uint2 g_WaT_l [64 * 64 * 32];
__device__ uint4 g_HH0_hm[256 * 64 * 32];
__device__ uint2 g_HH0_l [256 * 64 * 32];
__device__ uint4 g_HH1_hm[256 * 64 * 32];
__device__ uint2 g_HH1_l [256 * 64 * 32];
__device__ uint4 g_IH1_hm[256 * 64 * 32];
__device__ uint2 g_IH1_l [256 * 64 * 32];
__device__ uint4 g_IHC_hm[256 * 64 * 32];
__device__ uint2 g_IHC_l [256 * 64 * 32];
__device__ uint4 g_IH0_hm[256 * 64 * 32];
__device__ uint2 g_IH0_l [256 * 64 * 32];
// bf16 split operands for big projection GEMM
__device__ __nv_bfloat16 g_WH[VV * 1024];
__device__ __nv_bfloat16 g_WL[VV * 1024];
__device__ __nv_bfloat16 g_fH[2048 * 1024];
__device__ __nv_bfloat16 g_fL[2048 * 1024];

// ---------------- PTX helpers ----------------
__device__ __forceinline__ uint32_t smem_to_u32(const void* p) {
    uint32_t a;
    asm("{ .reg .u64 t; cvta.to.shared.u64 t, %1; cvt.u32.u64 %0, t; }" : "=r"(a) : "l"(p));
    return a;
}
#define CP16(dst, src) \
    asm volatile("cp.async.cg.shared.global [%0], [%1], 16;" \
                 :: "r"(dst), "l"(src) : "memory")
#define CP_COMMIT() asm volatile("cp.async.commit_group;" ::: "memory")
#define CP_WAIT0()  asm volatile("cp.async.wait_group 0;" ::: "memory")
#define CP_WAIT1()  asm volatile("cp.async.wait_group 1;" ::: "memory")

#define LDSM_X4(r0, r1, r2, r3, addr) \
    asm volatile("ldmatrix.sync.aligned.m8n8.x4.shared.b16 {%0,%1,%2,%3}, [%4];" \
                 : "=r"(r0), "=r"(r1), "=r"(r2), "=r"(r3) : "r"(addr))
#define LDSM_X2(r0, r1, addr) \
    asm volatile("ldmatrix.sync.aligned.m8n8.x2.shared.b16 {%0,%1}, [%2];" \
                 : "=r"(r0), "=r"(r1) : "r"(addr))

#define MMA_BF16(c, a0, a1, a2, a3, b0, b1) \
    asm volatile("mma.sync.aligned.m16n8k16.row.col.f32.bf16.bf16.f32 " \
                 "{%0,%1,%2,%3}, {%4,%5,%6,%7}, {%8,%9}, {%0,%1,%2,%3};" \
                 : "+f"((c)[0]), "+f"((c)[1]), "+f"((c)[2]), "+f"((c)[3]) \
                 : "r"(a0), "r"(a1), "r"(a2), "r"(a3), "r"(b0), "r"(b1))

#define MMA_TF32(c, a0, a1, a2, a3, b0, b1) \
    asm volatile("mma.sync.aligned.m16n8k8.row.col.f32.tf32.tf32.f32 " \
                 "{%0,%1,%2,%3}, {%4,%5,%6,%7}, {%8,%9}, {%0,%1,%2,%3};" \
                 : "+f"((c)[0]), "+f"((c)[1]), "+f"((c)[2]), "+f"((c)[3]) \
                 : "r"(a0), "r"(a1), "r"(a2), "r"(a3), "r"(b0), "r"(b1))

__device__ __forceinline__ uint32_t f2tf(float f) {
    uint32_t r;
    asm("cvt.rna.tf32.f32 %0, %1;" : "=r"(r) : "f"(f));
    return r;
}
__device__ __forceinline__ unsigned short bf16hi(float x) {
    return __bfloat16_as_ushort(__float2bfloat16(x));
}

// ---------------- utility kernels ----------------
__global__ void init_state_kernel(const float* __restrict__ hidden,
                                  const float* __restrict__ cell) {
    int i = blockIdx.x * blockDim.x + threadIdx.x;
    if (i == 0) g_barcnt = 0u;
    if (i < 2 * BATCH * HH) { g_h[i] = hidden[i]; g_c[i] = cell[i]; }
}

__global__ void tail_copy_kernel(float* __restrict__ out) {
    int i = blockIdx.x * blockDim.x + threadIdx.x;
    const long long OFF = (long long)BATCH * TT * VV;
    if (i < 2 * BATCH * HH) {
        out[OFF + i] = g_h[i];
        out[OFF + 2 * BATCH * HH + i] = g_c[i];
    }
}

__global__ void embed_kernel(const int* __restrict__ tgt,
                             const float* __restrict__ emb) {
    int blk = blockIdx.x;             // b*TT + t
    int b = blk >> 6, t = blk & 63;
    int idx = tgt[blk];
    int e = threadIdx.x * 4;
    float4 v;
    if (idx == 0) { v.x = v.y = v.z = v.w = 0.f; }
    else v = *reinterpret_cast<const float4*>(emb + (long long)idx * EE + e);
    *reinterpret_cast<float4*>(g_embF + (long long)(t * 32 + b) * 512 + e) = v;
}

__global__ void split_bf16_kernel(const float4* __restrict__ in,
                                  uint2* __restrict__ hi, uint2* __restrict__ lo, int n4) {
    for (int i = blockIdx.x * blockDim.x + threadIdx.x; i < n4; i += gridDim.x * blockDim.x) {
        float4 x = in[i];
        unsigned short h0 = bf16hi(x.x), h1 = bf16hi(x.y), h2 = bf16hi(x.z), h3 = bf16hi(x.w);
        unsigned short l0 = bf16hi(x.x - __bfloat162float(__ushort_as_bfloat16(h0)));
        unsigned short l1 = bf16hi(x.y - __bfloat162float(__ushort_as_bfloat16(h1)));
        unsigned short l2 = bf16hi(x.z - __bfloat162float(__ushort_as_bfloat16(h2)));
        unsigned short l3 = bf16hi(x.w - __bfloat162float(__ushort_as_bfloat16(h3)));
        uint2 hv, lv;
        hv.x = (uint32_t)h0 | ((uint32_t)h1 << 16);
        hv.y = (uint32_t)h2 | ((uint32_t)h3 << 16);
        lv.x = (uint32_t)l0 | ((uint32_t)l1 << 16);
        lv.y = (uint32_t)l2 | ((uint32_t)l3 << 16);
        hi[i] = hv; lo[i] = lv;
    }
}

// pack W[n][k] -> 3-way tf32 (H,M,L). grid (nt, 2), block 1024.
__global__ void pack3_kernel(const float* __restrict__ W, int sw,
                             uint4* __restrict__ dHM, uint2* __restrict__ dL) {
    int nt = blockIdx.x;
    int ki = blockIdx.y * 32 + (threadIdx.x >> 5);
    int lane = threadIdx.x & 31;
    int n = nt * 8 + (lane >> 2);
    int k = ki * 8 + (lane & 3);
    const float* w = W + (long long)n * sw + k;
    float v0 = w[0], v1 = w[4];
    uint32_t h0 = f2tf(v0); float r0 = v0 - __uint_as_float(h0);
    uint32_t m0 = f2tf(r0); float s0 = r0 - __uint_as_float(m0);
    uint32_t l0 = f2tf(s0);
    uint32_t h1 = f2tf(v1); float r1 = v1 - __uint_as_float(h1);
    uint32_t m1 = f2tf(r1); float s1 = r1 - __uint_as_float(m1);
    uint32_t l1 = f2tf(s1);
    int idx = (nt * 64 + ki) * 32 + lane;
    dHM[idx] = make_uint4(h0, h1, m0, m1);
    dL[idx]  = make_uint2(l0, l1);
}

// pack W^T (acts as W'[n][k] = W[k][n])
__global__ void pack3_t_kernel(const float* __restrict__ W, int sw,
                               uint4* __restrict__ dHM, uint2* __restrict__ dL) {
    int nt = blockIdx.x;
    int ki = blockIdx.y * 32 + (threadIdx.x >> 5);
    int lane = threadIdx.x & 31;
    int n = nt * 8 + (lane >> 2);
    int k = ki * 8 + (lane & 3);
    float v0 = W[(long long)k * sw + n];
    float v1 = W[(long long)(k + 4) * sw + n];
    uint32_t h0 = f2tf(v0); float r0 = v0 - __uint_as_float(h0);
    uint32_t m0 = f2tf(r0); float s0 = r0 - __uint_as_float(m0);
    uint32_t l0 = f2tf(s0);
    uint32_t h1 = f2tf(v1); float r1 = v1 - __uint_as_float(h1);
    uint32_t m1 = f2tf(r1); float s1 = r1 - __uint_as_float(m1);
    uint32_t l1 = f2tf(s1);
    int idx = (nt * 64 + ki) * 32 + lane;
    dHM[idx] = make_uint4(h0, h1, m0, m1);
    dL[idx]  = make_uint2(l0, l1);
}

// ---------------- warp-level M=32 x N=NJN*8 6-term 3xTF32 mma tile ----------
// C[32, n0 : n0+NJN*8] = A[32 x 512 fp32] @ Wpk^T over k8 range [k80, k80+nk8)
template <int NJN>
__device__ __forceinline__ void mma_row32_6t(
    const float* __restrict__ A,
    const uint4* __restrict__ wHM, const uint2* __restrict__ wL,
    int nt0, int k80, int nk8,
    float* __restrict__ C, int ldc, int n0, int lane)
{
    float acc[2][NJN][4];
    #pragma unroll
    for (int mi = 0; mi < 2; mi++)
        #pragma unroll
        for (int nj = 0; nj < NJN; nj++)
            #pragma unroll
            for (int v = 0; v < 4; v++) acc[mi][nj][v] = 0.f;

    const int r = lane >> 2;
    const int cc = lane & 3;
    const float* pa = A + r * 512 + k80 * 8 + cc;
    int base = (nt0 * 64 + k80) * 32 + lane;

    #pragma unroll 2
    for (int kk = 0; kk < nk8; kk++) {
        uint32_t aH[2][4], aM[2][4], aL[2][4];
        #pragma unroll
        for (int mi = 0; mi < 2; mi++) {
            const float* p = pa + mi * 16 * 512;
            float f0 = __ldcg(p);
            float f1 = __ldcg(p + 8 * 512);
            float f2 = __ldcg(p + 4);
            float f3 = __ldcg(p + 8 * 512 + 4);
            float fr;
            aH[mi][0] = f2tf(f0); fr = f0 - __uint_as_float(aH[mi][0]);
            aM[mi][0] = f2tf(fr); aL[mi][0] = f2tf(fr - __uint_as_float(aM[mi][0]));
            aH[mi][1] = f2tf(f1); fr = f1 - __uint_as_float(aH[mi][1]);
            aM[mi][1] = f2tf(fr); aL[mi][1] = f2tf(fr - __uint_as_float(aM[mi][1]));
            aH[mi][2] = f2tf(f2); fr = f2 - __uint_as_float(aH[mi][2]);
            aM[mi][2] = f2tf(fr); aL[mi][2] = f2tf(fr - __uint_as_float(aM[mi][2]));
            aH[mi][3] = f2tf(f3); fr = f3 - __uint_as_float(aH[mi][3]);
            aM[mi][3] = f2tf(fr); aL[mi][3] = f2tf(fr - __uint_as_float(aM[mi][3]));
        }
        #pragma unroll
        for (int nj = 0; nj < NJN; nj++) {
            uint4 hm = __ldg(wHM + base + nj * 2048);
            uint2 lo = __ldg(wL  + base + nj * 2048);
            #pragma unroll
            for (int mi = 0; mi < 2; mi++) {
                MMA_TF32(acc[mi][nj], aH[mi][0], aH[mi][1], aH[mi][2], aH[mi][3], hm.x, hm.y);
                MMA_TF32(acc[mi][nj], aM[mi][0], aM[mi][1], aM[mi][2], aM[mi][3], hm.x, hm.y);
                MMA_TF32(acc[mi][nj], aL[mi][0], aL[mi][1], aL[mi][2], aL[mi][3], hm.x, hm.y);
                MMA_TF32(acc[mi][nj], aH[mi][0], aH[mi][1], aH[mi][2], aH[mi][3], hm.z, hm.w);
                MMA_TF32(acc[mi][nj], aM[mi][0], aM[mi][1], aM[mi][2], aM[mi][3], hm.z, hm.w);
                MMA_TF32(acc[mi][nj], aH[mi][0], aH[mi][1], aH[mi][2], aH[mi][3], lo.x, lo.y);
            }
        }
        pa += 8; base += 32;
    }
    const int sc2 = cc * 2;
    #pragma unroll
    for (int mi = 0; mi < 2; mi++)
        #pragma unroll
        for (int nj = 0; nj < NJN; nj++) {
            int col = n0 + nj * 8 + sc2;
            *reinterpret_cast<float2*>(C + (mi * 16 + r) * ldc + col) =
                make_float2(acc[mi][nj][0], acc[mi][nj][1]);
            *reinterpret_cast<float2*>(C + (mi * 16 + 8 + r) * ldc + col) =
                make_float2(acc[mi][nj][2], acc[mi][nj][3]);
        }
}

// embpre: [2048,2048] = emb @ Wih0[:, :512]^T
__global__ __launch_bounds__(256)
void embpre_mma_kernel() {
    int g = blockIdx.x * 8 + (threadIdx.x >> 5);
    int lane = threadIdx.x & 31;
    int rb = g >> 6;
    int nt = g & 63;
    mma_row32_6t<4>(g_embF + rb * 32 * 512, g_IH0_hm, g_IH0_l, nt * 4, 0, 64,
                    g_embpre + (long long)rb * 32 * 2048, 2048, nt * 32, lane);
}

// encproj: [2048,512] = enc_flat @ W_a
__global__ __launch_bounds__(256)
void encproj_mma_kernel(const float* __restrict__ enc) {
    int g = blockIdx.x * 8 + (threadIdx.x >> 5);   // 0..1023
    int lane = threadIdx.x & 31;
    int rb = g >> 4;
    int nt = g & 15;
    mma_row32_6t<4>(enc + (long long)rb * 32 * 512, g_WaT_hm, g_WaT_l, nt * 4, 0, 64,
                    g_encproj + (long long)rb * 32 * 512, 512, nt * 32, lane);
}

// encIHC: [2048,2048] = enc_flat @ Wih0[:, 512:]^T
__global__ __launch_bounds__(256)
void encihc_mma_kernel(const float* __restrict__ enc) {
    int g = blockIdx.x * 8 + (threadIdx.x >> 5);
    int lane = threadIdx.x & 31;
    int rb = g >> 6;
    int nt = g & 63;
    mma_row32_6t<4>(enc + (long long)rb * 32 * 512, g_IHC_hm, g_IHC_l, nt * 4, 0, 64,
                    g_encIHC + (long long)rb * 32 * 2048, 2048, nt * 32, lane);
}

// ---------------- persistent recurrence (3 barriers/step) ----------------
// CTA roles: 0-31  = g1hh (phase A, smem) + g1ih+LSTM1 fused (phase DE)
//            32-63 = g0hh (phase A, smem) + LSTM0 (phase C)
//            64-95 = attention + ctx + g0ctx (phase A), b = cta-64
// smem layout (dynamic): ph = [8][32][18] (mma scratch, 18432B)
//                        rg = [4][32][18] (reduced gates, 9216B)
// attention CTAs reuse offset 0: h1s[512], sc[64], sred[2]
#define LDC 18
#define PHW 576     // 32*18

__device__ __forceinline__ float sigmf(float x) { return 1.f / (1.f + expf(-x)); }

__global__ __launch_bounds__(256, 1)
void decoder_persistent(const float* __restrict__ enc,
                        const float* __restrict__ b_ih0,
                        const float* __restrict__ b_hh0,
                        const float* __restrict__ b_ih1,
                        const float* __restrict__ b_hh1) {
    extern __shared__ float dsm[];
    float* ph = dsm;                 // 8 * 576
    float* rg = dsm + 8 * PHW;       // 4 * 576
    float* h1s = dsm;                // attn CTAs only
    float* sc = dsm + 512;
    float* sred = dsm + 580;

    const int cta = blockIdx.x;
    const int tid = threadIdx.x;
    const int lane = tid & 31;
    const int wid = tid >> 5;
    unsigned bar_t = 0;

    auto gbar = [&]() {
        __syncthreads();
        __threadfence();
        bar_t += NCTA;
        if (tid == 0) {
            atomicAdd(&g_barcnt, 1u);
            while (*(volatile unsigned*)&g_barcnt < bar_t) { }
        }
        __syncthreads();
    };

    const int q = wid >> 1;          // gate index for gemm warps
    const int kh = wid & 1;          // k-half

    for (int t = 0; t < TT; t++) {
        float* feat_t = g_feat + t * 32768;
        const float* ep = g_embpre + (long long)t * 65536;

        // ==== Phase A ====
        if (cta < 32) {
            // g1hh for u-tile cta (16 cols per gate), into smem
            mma_row32_6t<2>(g_h + 16384, g_HH1_hm, g_HH1_l,
                            q * 64 + cta * 2, kh * 32, 32,
                            ph + wid * PHW, LDC, 0, lane);
            __syncthreads();
            for (int i = tid; i < 2048; i += 256) {
                int q2 = i >> 9, e = i & 511, b = e >> 4, uu = e & 15;
                int si = b * LDC + uu;
                rg[q2 * PHW + si] = ph[(2 * q2) * PHW + si] + ph[(2 * q2 + 1) * PHW + si];
            }
        } else if (cta < 64) {
            // g0hh for u-tile cta-32
            int ct = cta - 32;
            mma_row32_6t<2>(g_h, g_HH0_hm, g_HH0_l,
                            q * 64 + ct * 2, kh * 32, 32,
                            ph + wid * PHW, LDC, 0, lane);
            __syncthreads();
            for (int i = tid; i < 2048; i += 256) {
                int q2 = i >> 9, e = i & 511, b = e >> 4, uu = e & 15;
                int si = b * LDC + uu;
                rg[q2 * PHW + si] = ph[(2 * q2) * PHW + si] + ph[(2 * q2 + 1) * PHW + si];
            }
        } else {
            // attention for b = cta-64
            const int b = cta - 64;
            #pragma unroll
            for (int r = 0; r < 2; r++) {
                int k = tid + r * 256;
                h1s[k] = __ldcg(g_h + 16384 + b * 512 + k);
            }
            __syncthreads();
            const float* epj = g_encproj + (long long)b * 64 * 512;
            #pragma unroll
            for (int si = 0; si < 8; si++) {
                int s = wid * 8 + si;
                const float* row = epj + s * 512;
                float sum = 0.f;
                for (int j = lane; j < 512; j += 32) sum += row[j] * h1s[j];
                #pragma unroll
                for (int o = 16; o; o >>= 1) sum += __shfl_down_sync(0xffffffffu, sum, o);
                if (lane == 0) sc[s] = sum;
            }
            __syncthreads();
            if (tid == 0) {
                float mx = sc[0];
                for (int s = 1; s < 64; s++) mx = fmaxf(mx, sc[s]);
                sred[0] = mx;
            }
            __syncthreads();
            if (tid < 64) sc[tid] = expf(sc[tid] - sred[0]);
            __syncthreads();
            if (tid == 0) {
                float sm = 0.f;
                for (int s = 0; s < 64; s++) sm += sc[s];
                sred[1] = 1.f / sm;
            }
            __syncthreads();
            const float inv = sred[1];

            // ctx: 2 cols/thread from enc
            {
                const float* encb = enc + (long long)b * SS * 512 + tid * 2;
                float c0 = 0.f, c1 = 0.f;
                #pragma unroll 8
                for (int s = 0; s < 64; s++) {
                    float w = sc[s];
                    float2 x = *reinterpret_cast<const float2*>(encb + s * 512);
                    c0 += w * x.x; c1 += w * x.y;
                }
                feat_t[b * 1024 + 512 + tid * 2]     = c0 * inv;
                feat_t[b * 1024 + 512 + tid * 2 + 1] = c1 * inv;
            }
            // g0ctx: 8 cols/thread from encIHC
            {
                const float* eb = g_encIHC + (long long)b * 64 * 2048 + tid * 8;
                float a8[8] = {0.f, 0.f, 0.f, 0.f, 0.f, 0.f, 0.f, 0.f};
                #pragma unroll 4
                for (int s = 0; s < 64; s++) {
                    float w = sc[s];
                    float4 x = *reinterpret_cast<const float4*>(eb + (long long)s * 2048);
                    float4 y = *reinterpret_cast<const float4*>(eb + (long long)s * 2048 + 4);
                    a8[0] += w * x.x; a8[1] += w * x.y; a8[2] += w * x.z; a8[3] += w * x.w;
                    a8[4] += w * y.x; a8[5] += w * y.y; a8[6] += w * y.z; a8[7] += w * y.w;
                }
                float* o = g_g0ctx + b * 2048 + tid * 8;
                #pragma unroll
                for (int j = 0; j < 8; j++) o[j] = a8[j] * inv;
            }
        }
        gbar();

        // ==== Phase C: LSTM0 (CTAs 32-63, u-tile ct = cta-32) ====
        if (cta >= 32 && cta < 64) {
            int ct = cta - 32;
            for (int i = tid; i < 512; i += 256) {
                int b = i >> 4, uu = i & 15, u = ct * 16 + uu;
                int si = b * LDC + uu;
                float gv[4];
                #pragma unroll
                for (int qq = 0; qq < 4; qq++) {
                    int o = b * 2048 + qq * 512 + u;
                    gv[qq] = rg[qq * PHW + si] + ep[o] + __ldcg(g_g0ctx + o)
                           + __ldg(b_ih0 + qq * 512 + u) + __ldg(b_hh0 + qq * 512 + u);
                }
                int idx = b * 512 + u;
                float cv = g_c[idx];
                float cn = sigmf(gv[1]) * cv + sigmf(gv[0]) * tanhf(gv[2]);
                float hn = sigmf(gv[3]) * tanhf(cn);
                g_c[idx] = cn;
                g_h[idx] = hn;
            }
        }
        gbar();

        // ==== Phase DE: g1ih + LSTM1 fused (CTAs 0-31, u-tile cta) ====
        if (cta < 32) {
            mma_row32_6t<2>(g_h, g_IH1_hm, g_IH1_l,
                            q * 64 + cta * 2, kh * 32, 32,
                            ph + wid * PHW, LDC, 0, lane);
            __syncthreads();
            for (int i = tid; i < 512; i += 256) {
                int b = i >> 4, uu = i & 15, u = cta * 16 + uu;
                int si = b * LDC + uu;
                float gv[4];
                #pragma unroll
                for (int qq = 0; qq < 4; qq++) {
                    gv[qq] = ph[(2 * qq) * PHW + si] + ph[(2 * qq + 1) * PHW + si]
                           + rg[qq * PHW + si]
                           + __ldg(b_ih1 + qq * 512 + u) + __ldg(b_hh1 + qq * 512 + u);
                }
                int idx = b * 512 + u;
                float cv = g_c[16384 + idx];
                float cn = sigmf(gv[1]) * cv + sigmf(gv[0]) * tanhf(gv[2]);
                float hn = sigmf(gv[3]) * tanhf(cn);
                g_c[16384 + idx] = cn;
                g_h[16384 + idx] = hn;
                feat_t[b * 1024 + u] = hn;
            }
        }
        gbar();
    }
}

// ---------------- big projection GEMM (3-term bf16, unchanged) ----------------
#define GK 1024
#define KC 32
#define NKC (GK / KC)
#define RST 40
#define BUF_BF16 (128 * RST)
#define STAGE_BF16 (4 * BUF_BF16)
#define GEMM_SMEM (2 * STAGE_BF16 * 2)

__global__ __launch_bounds__(256, 1)
void big_gemm_mma(const __nv_bfloat16* __restrict__ AH, const __nv_bfloat16* __restrict__ AL,
                  const __nv_bfloat16* __restrict__ BH, const __nv_bfloat16* __restrict__ BL,
                  const float* __restrict__ bias, float* __restrict__ out) {
    extern __shared__ __nv_bfloat16 sm[];
    const int tid = threadIdx.x;
    const int lane = tid & 31;
    const int wid = tid >> 5;
    const int wm = wid >> 1;
    const int wn = wid & 1;
    const int m0 = blockIdx.x * 128;
    const int n0 = blockIdx.y * 128;
    const uint32_t smem_base = smem_to_u32(sm);

    float acc[2][8][4];
    #pragma unroll
    for (int i = 0; i < 2; i++)
        #pragma unroll
        for (int j = 0; j < 8; j++)
            #pragma unroll
            for (int v = 0; v < 4; v++) acc[i][j][v] = 0.f;

    auto load_stage = [&](int st, int kc) {
        const uint32_t sb = smem_base + st * STAGE_BF16 * 2;
        const int k0 = kc * KC;
        #pragma unroll
        for (int r = 0; r < 2; r++) {
            int idx = tid + r * 256;
            int row = idx >> 2, c = idx & 3;
            uint32_t doff = (uint32_t)(row * RST + c * 8) * 2;
            long long aoff = (long long)(m0 + row) * GK + k0 + c * 8;
            long long boff = (long long)(n0 + row) * GK + k0 + c * 8;
            CP16(sb + doff,                AH + aoff);
            CP16(sb + BUF_BF16 * 2 + doff, AL + aoff);
            CP16(sb + BUF_BF16 * 4 + doff, BH + boff);
            CP16(sb + BUF_BF16 * 6 + doff, BL + boff);
        }
        CP_COMMIT();
    };

    load_stage(0, 0);

    for (int kc = 0; kc < NKC; kc++) {
        const int st = kc & 1;
        if (kc + 1 < NKC) { load_stage(st ^ 1, kc + 1); CP_WAIT1(); }
        else              { CP_WAIT0(); }
        __syncthreads();

        const uint32_t sb = smem_base + st * STAGE_BF16 * 2;
        uint32_t ah[2][2][4], al[2][2][4];
        #pragma unroll
        for (int i = 0; i < 2; i++)
            #pragma unroll
            for (int kk = 0; kk < 2; kk++) {
                uint32_t addr = sb + (uint32_t)((wm * 32 + i * 16 + (lane & 15)) * RST
                                                + kk * 16 + (lane >> 4) * 8) * 2;
                LDSM_X4(ah[i][kk][0], ah[i][kk][1], ah[i][kk][2], ah[i][kk][3], addr);
                LDSM_X4(al[i][kk][0], al[i][kk][1], al[i][kk][2], al[i][kk][3],
                        addr + BUF_BF16 * 2);
            }
        #pragma unroll
        for (int j = 0; j < 8; j++) {
            #pragma unroll
            for (int kk = 0; kk < 2; kk++) {
                uint32_t baddr = sb + BUF_BF16 * 4
                    + (uint32_t)((wn * 64 + j * 8 + (lane & 7)) * RST
                                 + kk * 16 + ((lane >> 3) & 1) * 8) * 2;
                uint32_t bh0, bh1, bl0, bl1;
                LDSM_X2(bh0, bh1, baddr);
                LDSM_X2(bl0, bl1, baddr + BUF_BF16 * 2);
                #pragma unroll
                for (int i = 0; i < 2; i++) {
                    MMA_BF16(acc[i][j], ah[i][kk][0], ah[i][kk][1], ah[i][kk][2], ah[i][kk][3], bh0, bh1);
                    MMA_BF16(acc[i][j], al[i][kk][0], al[i][kk][1], al[i][kk][2], al[i][kk][3], bh0, bh1);
                    MMA_BF16(acc[i][j], ah[i][kk][0], ah[i][kk][1], ah[i][kk][2], ah[i][kk][3], bl0, bl1);
                }
            }
        }
        __syncthreads();
    }

    #pragma unroll
    for (int i = 0; i < 2; i++) {
        int mA = m0 + wm * 32 + i * 16 + (lane >> 2);
        int mB = mA + 8;
        int tA = mA >> 5, bA = mA & 31;
        int tB = mB >> 5, bB = mB & 31;
        float* rowA = out + (long long)((bA << 6) + tA) * VV;
        float* rowB = out + (long long)((bB << 6) + tB) * VV;
        #pragma unroll
        for (int j = 0; j < 8; j++) {
            int n = n0 + wn * 64 + j * 8 + (lane & 3) * 2;
            float bv0 = bias[n], bv1 = bias[n + 1];
            float2 vA = make_float2(acc[i][j][0] + bv0, acc[i][j][1] + bv1);
            float2 vB = make_float2(acc[i][j][2] + bv0, acc[i][j][3] + bv1);
            *reinterpret_cast<float2*>(rowA + n) = vA;
            *reinterpret_cast<float2*>(rowB + n) = vB;
        }
    }
}

// ---------------- host launcher ----------------
extern "C" void kernel_launch(void* const* d_in, const int* in_sizes, int n_in,
                              void* d_out, int out_size) {
    const int*   tgt    = (const int*)  d_in[0];
    const float* enc    = (const float*)d_in[1];
    const float* hidden = (const float*)d_in[2];
    const float* cell   = (const float*)d_in[3];
    const float* emb    = (const float*)d_in[4];
    const float* W_a    = (const float*)d_in[5];
    const float* W_ih0  = (const float*)d_in[6];
    const float* W_hh0  = (const float*)d_in[7];
    const float* b_ih0  = (const float*)d_in[8];
    const float* b_hh0  = (const float*)d_in[9];
    const float* W_ih1  = (const float*)d_in[10];
    const float* W_hh1  = (const float*)d_in[11];
    const float* b_ih1  = (const float*)d_in[12];
    const float* b_hh1  = (const float*)d_in[13];
    const float* W_out  = (const float*)d_in[14];
    const float* b_out  = (const float*)d_in[15];
    float* out = (float*)d_out;

    float *p_feat;
    __nv_bfloat16 *p_WH, *p_WL, *p_fH, *p_fL;
    uint4 *hmWaT, *hmHH0, *hmHH1, *hmIH1, *hmIHC, *hmIH0;
    uint2 *lWaT, *lHH0, *lHH1, *lIH1, *lIHC, *lIH0;
    cudaGetSymbolAddress((void**)&p_feat, g_feat);
    cudaGetSymbolAddress((void**)&p_WH,   g_WH);
    cudaGetSymbolAddress((void**)&p_WL,   g_WL);
    cudaGetSymbolAddress((void**)&p_fH,   g_fH);
    cudaGetSymbolAddress((void**)&p_fL,   g_fL);
    cudaGetSymbolAddress((void**)&hmWaT,  g_WaT_hm);  cudaGetSymbolAddress((void**)&lWaT, g_WaT_l);
    cudaGetSymbolAddress((void**)&hmHH0,  g_HH0_hm);  cudaGetSymbolAddress((void**)&lHH0, g_HH0_l);
    cudaGetSymbolAddress((void**)&hmHH1,  g_HH1_hm);  cudaGetSymbolAddress((void**)&lHH1, g_HH1_l);
    cudaGetSymbolAddress((void**)&hmIH1,  g_IH1_hm);  cudaGetSymbolAddress((void**)&lIH1, g_IH1_l);
    cudaGetSymbolAddress((void**)&hmIHC,  g_IHC_hm);  cudaGetSymbolAddress((void**)&lIHC, g_IHC_l);
    cudaGetSymbolAddress((void**)&hmIH0,  g_IH0_hm);  cudaGetSymbolAddress((void**)&lIH0, g_IH0_l);

    init_state_kernel<<<64, 512>>>(hidden, cell);
    embed_kernel<<<BATCH * TT, 128>>>(tgt, emb);

    // pack weights as 3-way tf32
    pack3_t_kernel<<<dim3(64, 2),  1024>>>(W_a,        512,  hmWaT, lWaT);
    pack3_kernel<<<dim3(256, 2), 1024>>>(W_hh0,        512,  hmHH0, lHH0);
    pack3_kernel<<<dim3(256, 2), 1024>>>(W_hh1,        512,  hmHH1, lHH1);
    pack3_kernel<<<dim3(256, 2), 1024>>>(W_ih1,        512,  hmIH1, lIH1);
    pack3_kernel<<<dim3(256, 2), 1024>>>(W_ih0 + 512,  1024, hmIHC, lIHC);
    pack3_kernel<<<dim3(256, 2), 1024>>>(W_ih0,        1024, hmIH0, lIH0);

    // precompute emb @ Wih0[:, :512]^T, enc @ W_a, enc @ Wih0[:,512:]^T (6-term)
    embpre_mma_kernel<<<512, 256>>>();
    encproj_mma_kernel<<<128, 256>>>(enc);
    encihc_mma_kernel<<<512, 256>>>(enc);

    // fused persistent recurrence (3 barriers/step, 96 CTAs)
    decoder_persistent<<<NCTA, 256, (8 + 4) * PHW * 4>>>(enc, b_ih0, b_hh0, b_ih1, b_hh1);

    // split W_out and feat for big GEMM
    split_bf16_kernel<<<4096, 256>>>((const float4*)W_out, (uint2*)p_WH, (uint2*)p_WL,
                                     VV * 1024 / 4);
    split_bf16_kernel<<<2048, 256>>>((const float4*)p_feat, (uint2*)p_fH, (uint2*)p_fL,
                                     2048 * 1024 / 4);

    // tensor-core projection
    cudaFuncSetAttribute(big_gemm_mma, cudaFuncAttributeMaxDynamicSharedMemorySize, GEMM_SMEM);
    big_gemm_mma<<<dim3(16, VV / 128), 256, GEMM_SMEM>>>(p_fH, p_fL, p_WH, p_WL, b_out, out);

    tail_copy_kernel<<<64, 512>>>(out);
}

// round 12
// speedup vs baseline: 1.3355x; 1.3355x over previous
#include <cuda_runtime.h>
#include <cuda_bf16.h>
#include <math.h>
#include <stdint.h>

// Problem constants
#define BATCH 32
#define TT 64
#define SS 64
#define VV 32000
#define EE 512
#define HH 512
#define NCTA 128

// ---------------- device scratch ----------------
__device__ float g_embF[2048 * 512];             // embedded fp32, row = t*32+b
__device__ float g_encproj[2048 * 512];          // enc @ W_a, row = b*64+s
__device__ float g_encIHC[2048 * 2048];          // enc @ Wih0[:,512:]^T
__device__ float g_h[2 * BATCH * HH];            // fp32 state [h0 | h1]
__device__ float g_c[2 * BATCH * HH];
__device__ float g_feat[TT * BATCH * 1024];      // [t][b][ h1 | ctx ]
__device__ float g_embpre[TT * BATCH * 2048];    // emb @ Wih0[:, :512]^T
__device__ float g_g0hh[BATCH * 2048];
__device__ float g_g1hh[BATCH * 2048];
__device__ float g_g1ih[BATCH * 2048];
__device__ float g_g0ctx[BATCH * 2048];
__device__ unsigned g_barcnt;
// bf16 split operands for big projection GEMM
__device__ __nv_bfloat16 g_WH[VV * 1024];
__device__ __nv_bfloat16 g_WL[VV * 1024];
__device__ __nv_bfloat16 g_fH[2048 * 1024];
__device__ __nv_bfloat16 g_fL[2048 * 1024];

// ---------------- PTX helpers ----------------
__device__ __forceinline__ uint32_t smem_to_u32(const void* p) {
    uint32_t a;
    asm("{ .reg .u64 t; cvta.to.shared.u64 t, %1; cvt.u32.u64 %0, t; }" : "=r"(a) : "l"(p));
    return a;
}
#define CP16(dst, src) \
    asm volatile("cp.async.cg.shared.global [%0], [%1], 16;" \
                 :: "r"(dst), "l"(src) : "memory")
#define CP_COMMIT() asm volatile("cp.async.commit_group;" ::: "memory")
#define CP_WAIT0()  asm volatile("cp.async.wait_group 0;" ::: "memory")
#define CP_WAIT1()  asm volatile("cp.async.wait_group 1;" ::: "memory")

#define LDSM_X4(r0, r1, r2, r3, addr) \
    asm volatile("ldmatrix.sync.aligned.m8n8.x4.shared.b16 {%0,%1,%2,%3}, [%4];" \
                 : "=r"(r0), "=r"(r1), "=r"(r2), "=r"(r3) : "r"(addr))
#define LDSM_X2(r0, r1, addr) \
    asm volatile("ldmatrix.sync.aligned.m8n8.x2.shared.b16 {%0,%1}, [%2];" \
                 : "=r"(r0), "=r"(r1) : "r"(addr))

#define MMA_BF16(c, a0, a1, a2, a3, b0, b1) \
    asm volatile("mma.sync.aligned.m16n8k16.row.col.f32.bf16.bf16.f32 " \
                 "{%0,%1,%2,%3}, {%4,%5,%6,%7}, {%8,%9}, {%0,%1,%2,%3};" \
                 : "+f"((c)[0]), "+f"((c)[1]), "+f"((c)[2]), "+f"((c)[3]) \
                 : "r"(a0), "r"(a1), "r"(a2), "r"(a3), "r"(b0), "r"(b1))

__device__ __forceinline__ unsigned short bf16hi(float x) {
    return __bfloat16_as_ushort(__float2bfloat16(x));
}

// ---------------- utility kernels ----------------
__global__ void init_state_kernel(const float* __restrict__ hidden,
                                  const float* __restrict__ cell) {
    int i = blockIdx.x * blockDim.x + threadIdx.x;
    if (i == 0) g_barcnt = 0u;
    if (i < 2 * BATCH * HH) { g_h[i] = hidden[i]; g_c[i] = cell[i]; }
}

__global__ void tail_copy_kernel(float* __restrict__ out) {
    int i = blockIdx.x * blockDim.x + threadIdx.x;
    const long long OFF = (long long)BATCH * TT * VV;
    if (i < 2 * BATCH * HH) {
        out[OFF + i] = g_h[i];
        out[OFF + 2 * BATCH * HH + i] = g_c[i];
    }
}

__global__ void embed_kernel(const int* __restrict__ tgt,
                             const float* __restrict__ emb) {
    int blk = blockIdx.x;             // b*TT + t
    int b = blk >> 6, t = blk & 63;
    int idx = tgt[blk];
    int e = threadIdx.x * 4;
    float4 v;
    if (idx == 0) { v.x = v.y = v.z = v.w = 0.f; }
    else v = *reinterpret_cast<const float4*>(emb + (long long)idx * EE + e);
    *reinterpret_cast<float4*>(g_embF + (long long)(t * 32 + b) * 512 + e) = v;
}

__global__ void split_bf16_kernel(const float4* __restrict__ in,
                                  uint2* __restrict__ hi, uint2* __restrict__ lo, int n4) {
    for (int i = blockIdx.x * blockDim.x + threadIdx.x; i < n4; i += gridDim.x * blockDim.x) {
        float4 x = in[i];
        unsigned short h0 = bf16hi(x.x), h1 = bf16hi(x.y), h2 = bf16hi(x.z), h3 = bf16hi(x.w);
        unsigned short l0 = bf16hi(x.x - __bfloat162float(__ushort_as_bfloat16(h0)));
        unsigned short l1 = bf16hi(x.y - __bfloat162float(__ushort_as_bfloat16(h1)));
        unsigned short l2 = bf16hi(x.z - __bfloat162float(__ushort_as_bfloat16(h2)));
        unsigned short l3 = bf16hi(x.w - __bfloat162float(__ushort_as_bfloat16(h3)));
        uint2 hv, lv;
        hv.x = (uint32_t)h0 | ((uint32_t)h1 << 16);
        hv.y = (uint32_t)h2 | ((uint32_t)h3 << 16);
        lv.x = (uint32_t)l0 | ((uint32_t)l1 << 16);
        lv.y = (uint32_t)l2 | ((uint32_t)l3 << 16);
        hi[i] = hv; lo[i] = lv;
    }
}

// ---------------- fp32 prep GEMM (NT): C = A[:,512] @ B^T -------------------
// grid (ncols/64, nrows/64), block 256.
__global__ __launch_bounds__(256)
void gemm64_nt_f32(const float* __restrict__ A,
                   const float* __restrict__ B, int ldb,
                   float* __restrict__ C, int ldc) {
    __shared__ __align__(16) float As[16][68];
    __shared__ __align__(16) float Bs[16][68];
    const int tid = threadIdx.x;
    const int m0 = blockIdx.y * 64, n0 = blockIdx.x * 64;
    const int lr = tid >> 2, lc = (tid & 3) * 4;
    const int tm = (tid >> 4) * 4, tn = (tid & 15) * 4;
    float acc[4][4] = {};
    for (int k0 = 0; k0 < 512; k0 += 16) {
        float4 av = *reinterpret_cast<const float4*>(A + (long long)(m0 + lr) * 512 + k0 + lc);
        As[lc + 0][lr] = av.x; As[lc + 1][lr] = av.y; As[lc + 2][lr] = av.z; As[lc + 3][lr] = av.w;
        float4 wv = *reinterpret_cast<const float4*>(B + (long long)(n0 + lr) * ldb + k0 + lc);
        Bs[lc + 0][lr] = wv.x; Bs[lc + 1][lr] = wv.y; Bs[lc + 2][lr] = wv.z; Bs[lc + 3][lr] = wv.w;
        __syncthreads();
        #pragma unroll
        for (int kk = 0; kk < 16; kk++) {
            float4 a = *reinterpret_cast<const float4*>(&As[kk][tm]);
            float4 b = *reinterpret_cast<const float4*>(&Bs[kk][tn]);
            acc[0][0] += a.x * b.x; acc[0][1] += a.x * b.y; acc[0][2] += a.x * b.z; acc[0][3] += a.x * b.w;
            acc[1][0] += a.y * b.x; acc[1][1] += a.y * b.y; acc[1][2] += a.y * b.z; acc[1][3] += a.y * b.w;
            acc[2][0] += a.z * b.x; acc[2][1] += a.z * b.y; acc[2][2] += a.z * b.z; acc[2][3] += a.z * b.w;
            acc[3][0] += a.w * b.x; acc[3][1] += a.w * b.y; acc[3][2] += a.w * b.z; acc[3][3] += a.w * b.w;
        }
        __syncthreads();
    }
    #pragma unroll
    for (int i = 0; i < 4; i++) {
        float4 o = make_float4(acc[i][0], acc[i][1], acc[i][2], acc[i][3]);
        *reinterpret_cast<float4*>(C + (long long)(m0 + tm + i) * ldc + n0 + tn) = o;
    }
}

// ---------------- fp32 prep GEMM (NN): C = A[:,512] @ B ---------------------
// C[r, j] = sum_k A[r,k] * B[k*ldb + j].  grid (ncols/64, nrows/64), block 256.
__global__ __launch_bounds__(256)
void gemm64_nn_f32(const float* __restrict__ A,
                   const float* __restrict__ B, int ldb,
                   float* __restrict__ C, int ldc) {
    __shared__ __align__(16) float As[16][68];
    __shared__ __align__(16) float Bs[16][68];
    const int tid = threadIdx.x;
    const int m0 = blockIdx.y * 64, n0 = blockIdx.x * 64;
    const int lr = tid >> 2, lc = (tid & 3) * 4;        // A load: row lr, 4 k's
    const int kr = tid >> 4, jc = (tid & 15) * 4;       // B load: k-row kr, 4 j's
    const int tm = (tid >> 4) * 4, tn = (tid & 15) * 4;
    float acc[4][4] = {};
    for (int k0 = 0; k0 < 512; k0 += 16) {
        float4 av = *reinterpret_cast<const float4*>(A + (long long)(m0 + lr) * 512 + k0 + lc);
        As[lc + 0][lr] = av.x; As[lc + 1][lr] = av.y; As[lc + 2][lr] = av.z; As[lc + 3][lr] = av.w;
        float4 bv = *reinterpret_cast<const float4*>(B + (long long)(k0 + kr) * ldb + n0 + jc);
        *reinterpret_cast<float4*>(&Bs[kr][jc]) = bv;
        __syncthreads();
        #pragma unroll
        for (int kk = 0; kk < 16; kk++) {
            float4 a = *reinterpret_cast<const float4*>(&As[kk][tm]);
            float4 b = *reinterpret_cast<const float4*>(&Bs[kk][tn]);
            acc[0][0] += a.x * b.x; acc[0][1] += a.x * b.y; acc[0][2] += a.x * b.z; acc[0][3] += a.x * b.w;
            acc[1][0] += a.y * b.x; acc[1][1] += a.y * b.y; acc[1][2] += a.y * b.z; acc[1][3] += a.y * b.w;
            acc[2][0] += a.z * b.x; acc[2][1] += a.z * b.y; acc[2][2] += a.z * b.z; acc[2][3] += a.z * b.w;
            acc[3][0] += a.w * b.x; acc[3][1] += a.w * b.y; acc[3][2] += a.w * b.z; acc[3][3] += a.w * b.w;
        }
        __syncthreads();
    }
    #pragma unroll
    for (int i = 0; i < 4; i++) {
        float4 o = make_float4(acc[i][0], acc[i][1], acc[i][2], acc[i][3]);
        *reinterpret_cast<float4*>(C + (long long)(m0 + tm + i) * ldc + n0 + tn) = o;
    }
}

// ---------------- persistent recurrence (fp32, 4 cheap barriers/step) -------
#define SA_FLOATS (512 * 33)
#define DSM_BYTES ((SA_FLOATS + 32 * 512) * 4)

__device__ __forceinline__ float sigmf(float x) { return 1.f / (1.f + expf(-x)); }

// C[32 rows, 32 cols @ n0] = A[32x512] @ W[n0+j, :]^T   (fp32, full K=512)
__device__ __forceinline__ void fgemm_tile32(
    const float* __restrict__ A, const float* __restrict__ W, int sw, int n0,
    float* __restrict__ C, int ldc, float* sA, float* sB, int tid)
{
    const float* Wr = W + (long long)n0 * sw;
    for (int i = tid; i < 32 * 128; i += 256) {
        int col = i >> 7, kq = (i & 127) << 2;
        float4 v = __ldg(reinterpret_cast<const float4*>(Wr + (long long)col * sw + kq));
        *reinterpret_cast<float4*>(sB + col * 512 + kq) = v;
    }
    for (int i = tid; i < 32 * 128; i += 256) {
        int b = i >> 7, kq = (i & 127) << 2;
        float4 v = __ldcg(reinterpret_cast<const float4*>(A + b * 512 + kq));
        sA[(kq + 0) * 33 + b] = v.x;
        sA[(kq + 1) * 33 + b] = v.y;
        sA[(kq + 2) * 33 + b] = v.z;
        sA[(kq + 3) * 33 + b] = v.w;
    }
    __syncthreads();
    const int b = tid & 31, cg = tid >> 5;
    float a0c = 0.f, a1c = 0.f, a2c = 0.f, a3c = 0.f;
    const float* bp = sB + cg * 4 * 512;
    #pragma unroll 4
    for (int k = 0; k < 512; k += 4) {
        float a0 = sA[(k + 0) * 33 + b];
        float a1 = sA[(k + 1) * 33 + b];
        float a2 = sA[(k + 2) * 33 + b];
        float a3 = sA[(k + 3) * 33 + b];
        float4 b0 = *reinterpret_cast<const float4*>(bp + k);
        float4 b1 = *reinterpret_cast<const float4*>(bp + 512 + k);
        float4 b2 = *reinterpret_cast<const float4*>(bp + 1024 + k);
        float4 b3 = *reinterpret_cast<const float4*>(bp + 1536 + k);
        a0c += a0 * b0.x; a0c += a1 * b0.y; a0c += a2 * b0.z; a0c += a3 * b0.w;
        a1c += a0 * b1.x; a1c += a1 * b1.y; a1c += a2 * b1.z; a1c += a3 * b1.w;
        a2c += a0 * b2.x; a2c += a1 * b2.y; a2c += a2 * b2.z; a2c += a3 * b2.w;
        a3c += a0 * b3.x; a3c += a1 * b3.y; a3c += a2 * b3.z; a3c += a3 * b3.w;
    }
    __stcg(reinterpret_cast<float4*>(C + (long long)b * ldc + n0 + cg * 4),
           make_float4(a0c, a1c, a2c, a3c));
}

__global__ __launch_bounds__(256, 1)
void decoder_persistent(const float* __restrict__ enc,
                        const float* __restrict__ W_hh0,
                        const float* __restrict__ W_hh1,
                        const float* __restrict__ W_ih1,
                        const float* __restrict__ b_ih0,
                        const float* __restrict__ b_hh0,
                        const float* __restrict__ b_ih1,
                        const float* __restrict__ b_hh1) {
    extern __shared__ float dsm[];
    float* sA = dsm;
    float* sB = dsm + SA_FLOATS;
    float* h1s = dsm;                // attn overlay
    float* sc = dsm + 512;
    float* sred = dsm + 580;

    const int cta = blockIdx.x;
    const int tid = threadIdx.x;
    const int lane = tid & 31;
    const int wid = tid >> 5;
    unsigned bar_t = 0;
    unsigned* barp = &g_barcnt;

    auto gbar = [&]() {
        __syncthreads();
        bar_t += NCTA;
        if (tid == 0) {
            asm volatile("red.release.gpu.global.add.u32 [%0], 1;"
                         :: "l"(barp) : "memory");
            unsigned v;
            do {
                asm volatile("ld.acquire.gpu.global.u32 %0, [%1];"
                             : "=r"(v) : "l"(barp) : "memory");
            } while (v < bar_t);
        }
        __syncthreads();
    };

    float* h0 = g_h;
    float* h1 = g_h + 16384;

    for (int t = 0; t < TT; t++) {
        float* feat_t = g_feat + t * 32768;
        const float* ep = g_embpre + (long long)t * 65536;

        // ==== Phase A: g0hh (0-63) | attn (64-95) | g1hh half1 (96-127) ====
        if (cta < 64) {
            fgemm_tile32(h0, W_hh0, 512, cta * 32, g_g0hh, 2048, sA, sB, tid);
        } else if (cta < 96) {
            const int b = cta - 64;
            #pragma unroll
            for (int r = 0; r < 2; r++) {
                int k = tid + r * 256;
                h1s[k] = __ldcg(h1 + b * 512 + k);
            }
            __syncthreads();
            const float* epj = g_encproj + (long long)b * 64 * 512;
            #pragma unroll
            for (int si = 0; si < 8; si++) {
                int s = wid * 8 + si;
                const float* row = epj + s * 512;
                float sum = 0.f;
                for (int j = lane; j < 512; j += 32) sum += row[j] * h1s[j];
                #pragma unroll
                for (int o = 16; o; o >>= 1) sum += __shfl_down_sync(0xffffffffu, sum, o);
                if (lane == 0) sc[s] = sum;
            }
            __syncthreads();
            if (tid == 0) {
                float mx = sc[0];
                for (int s = 1; s < 64; s++) mx = fmaxf(mx, sc[s]);
                sred[0] = mx;
            }
            __syncthreads();
            if (tid < 64) sc[tid] = expf(sc[tid] - sred[0]);
            __syncthreads();
            if (tid == 0) {
                float sm = 0.f;
                for (int s = 0; s < 64; s++) sm += sc[s];
                sred[1] = 1.f / sm;
            }
            __syncthreads();
            const float inv = sred[1];

            // ctx: 2 cols/thread
            {
                const float* encb = enc + (long long)b * SS * 512 + tid * 2;
                float c0 = 0.f, c1 = 0.f;
                #pragma unroll 8
                for (int s = 0; s < 64; s++) {
                    float w = sc[s];
                    float2 x = *reinterpret_cast<const float2*>(encb + s * 512);
                    c0 += w * x.x; c1 += w * x.y;
                }
                feat_t[b * 1024 + 512 + tid * 2]     = c0 * inv;
                feat_t[b * 1024 + 512 + tid * 2 + 1] = c1 * inv;
            }
            // g0ctx: 8 cols/thread from encIHC
            {
                const float* eb = g_encIHC + (long long)b * 64 * 2048 + tid * 8;
                float a8[8] = {0.f, 0.f, 0.f, 0.f, 0.f, 0.f, 0.f, 0.f};
                #pragma unroll 4
                for (int s = 0; s < 64; s++) {
                    float w = sc[s];
                    float4 x = *reinterpret_cast<const float4*>(eb + (long long)s * 2048);
                    float4 y = *reinterpret_cast<const float4*>(eb + (long long)s * 2048 + 4);
                    a8[0] += w * x.x; a8[1] += w * x.y; a8[2] += w * x.z; a8[3] += w * x.w;
                    a8[4] += w * y.x; a8[5] += w * y.y; a8[6] += w * y.z; a8[7] += w * y.w;
                }
                float* o = g_g0ctx + b * 2048 + tid * 8;
                #pragma unroll
                for (int j = 0; j < 8; j++) __stcg(o + j, a8[j] * inv);
            }
        } else {
            fgemm_tile32(h1, W_hh1, 512, (cta - 96) * 32, g_g1hh, 2048, sA, sB, tid);
        }
        gbar();

        // ==== Phase C: LSTM0 (128 CTAs x 128 threads) ====
        if (tid < 128) {
            int idx = cta * 128 + tid;
            int b = idx >> 9, u = idx & 511;
            int gg0 = b * 2048 + u;
            float gv[4];
            #pragma unroll
            for (int q = 0; q < 4; q++) {
                int o = gg0 + q * 512;
                gv[q] = ep[o] + __ldcg(g_g0hh + o) + __ldcg(g_g0ctx + o)
                      + __ldg(b_ih0 + q * 512 + u) + __ldg(b_hh0 + q * 512 + u);
            }
            float cv = g_c[idx];
            float cn = sigmf(gv[1]) * cv + sigmf(gv[0]) * tanhf(gv[2]);
            float hn = sigmf(gv[3]) * tanhf(cn);
            g_c[idx] = cn;
            __stcg(h0 + idx, hn);
        }
        gbar();

        // ==== Phase D: g1hh half2 (0-31) | g1ih (32-95) ====
        if (cta < 32) {
            fgemm_tile32(h1, W_hh1, 512, 1024 + cta * 32, g_g1hh, 2048, sA, sB, tid);
        } else if (cta < 96) {
            fgemm_tile32(h0, W_ih1, 512, (cta - 32) * 32, g_g1ih, 2048, sA, sB, tid);
        }
        gbar();

        // ==== Phase E: LSTM1 + feat write ====
        if (tid < 128) {
            int idx = cta * 128 + tid;
            int b = idx >> 9, u = idx & 511;
            int gg0 = b * 2048 + u;
            float gv[4];
            #pragma unroll
            for (int q = 0; q < 4; q++) {
                int o = gg0 + q * 512;
                gv[q] = __ldcg(g_g1hh + o) + __ldcg(g_g1ih + o)
                      + __ldg(b_ih1 + q * 512 + u) + __ldg(b_hh1 + q * 512 + u);
            }
            float cv = g_c[16384 + idx];
            float cn = sigmf(gv[1]) * cv + sigmf(gv[0]) * tanhf(gv[2]);
            float hn = sigmf(gv[3]) * tanhf(cn);
            g_c[16384 + idx] = cn;
            __stcg(h1 + idx, hn);
            feat_t[b * 1024 + u] = hn;
        }
        gbar();
    }
}

// ---------------- big projection GEMM (3-term bf16, unchanged) ----------------
#define GK 1024
#define KC 32
#define NKC (GK / KC)
#define RST 40
#define BUF_BF16 (128 * RST)
#define STAGE_BF16 (4 * BUF_BF16)
#define GEMM_SMEM (2 * STAGE_BF16 * 2)

__global__ __launch_bounds__(256, 1)
void big_gemm_mma(const __nv_bfloat16* __restrict__ AH, const __nv_bfloat16* __restrict__ AL,
                  const __nv_bfloat16* __restrict__ BH, const __nv_bfloat16* __restrict__ BL,
                  const float* __restrict__ bias, float* __restrict__ out) {
    extern __shared__ __nv_bfloat16 sm[];
    const int tid = threadIdx.x;
    const int lane = tid & 31;
    const int wid = tid >> 5;
    const int wm = wid >> 1;
    const int wn = wid & 1;
    const int m0 = blockIdx.x * 128;
    const int n0 = blockIdx.y * 128;
    const uint32_t smem_base = smem_to_u32(sm);

    float acc[2][8][4];
    #pragma unroll
    for (int i = 0; i < 2; i++)
        #pragma unroll
        for (int j = 0; j < 8; j++)
            #pragma unroll
            for (int v = 0; v < 4; v++) acc[i][j][v] = 0.f;

    auto load_stage = [&](int st, int kc) {
        const uint32_t sb = smem_base + st * STAGE_BF16 * 2;
        const int k0 = kc * KC;
        #pragma unroll
        for (int r = 0; r < 2; r++) {
            int idx = tid + r * 256;
            int row = idx >> 2, c = idx & 3;
            uint32_t doff = (uint32_t)(row * RST + c * 8) * 2;
            long long aoff = (long long)(m0 + row) * GK + k0 + c * 8;
            long long boff = (long long)(n0 + row) * GK + k0 + c * 8;
            CP16(sb + doff,                AH + aoff);
            CP16(sb + BUF_BF16 * 2 + doff, AL + aoff);
            CP16(sb + BUF_BF16 * 4 + doff, BH + boff);
            CP16(sb + BUF_BF16 * 6 + doff, BL + boff);
        }
        CP_COMMIT();
    };

    load_stage(0, 0);

    for (int kc = 0; kc < NKC; kc++) {
        const int st = kc & 1;
        if (kc + 1 < NKC) { load_stage(st ^ 1, kc + 1); CP_WAIT1(); }
        else              { CP_WAIT0(); }
        __syncthreads();

        const uint32_t sb = smem_base + st * STAGE_BF16 * 2;
        uint32_t ah[2][2][4], al[2][2][4];
        #pragma unroll
        for (int i = 0; i < 2; i++)
            #pragma unroll
            for (int kk = 0; kk < 2; kk++) {
                uint32_t addr = sb + (uint32_t)((wm * 32 + i * 16 + (lane & 15)) * RST
                                                + kk * 16 + (lane >> 4) * 8) * 2;
                LDSM_X4(ah[i][kk][0], ah[i][kk][1], ah[i][kk][2], ah[i][kk][3], addr);
                LDSM_X4(al[i][kk][0], al[i][kk][1], al[i][kk][2], al[i][kk][3],
                        addr + BUF_BF16 * 2);
            }
        #pragma unroll
        for (int j = 0; j < 8; j++) {
            #pragma unroll
            for (int kk = 0; kk < 2; kk++) {
                uint32_t baddr = sb + BUF_BF16 * 4
                    + (uint32_t)((wn * 64 + j * 8 + (lane & 7)) * RST
                                 + kk * 16 + ((lane >> 3) & 1) * 8) * 2;
                uint32_t bh0, bh1, bl0, bl1;
                LDSM_X2(bh0, bh1, baddr);
                LDSM_X2(bl0, bl1, baddr + BUF_BF16 * 2);
                #pragma unroll
                for (int i = 0; i < 2; i++) {
                    MMA_BF16(acc[i][j], ah[i][kk][0], ah[i][kk][1], ah[i][kk][2], ah[i][kk][3], bh0, bh1);
                    MMA_BF16(acc[i][j], al[i][kk][0], al[i][kk][1], al[i][kk][2], al[i][kk][3], bh0, bh1);
                    MMA_BF16(acc[i][j], ah[i][kk][0], ah[i][kk][1], ah[i][kk][2], ah[i][kk][3], bl0, bl1);
                }
            }
        }
        __syncthreads();
    }

    #pragma unroll
    for (int i = 0; i < 2; i++) {
        int mA = m0 + wm * 32 + i * 16 + (lane >> 2);
        int mB = mA + 8;
        int tA = mA >> 5, bA = mA & 31;
        int tB = mB >> 5, bB = mB & 31;
        float* rowA = out + (long long)((bA << 6) + tA) * VV;
        float* rowB = out + (long long)((bB << 6) + tB) * VV;
        #pragma unroll
        for (int j = 0; j < 8; j++) {
            int n = n0 + wn * 64 + j * 8 + (lane & 3) * 2;
            float bv0 = bias[n], bv1 = bias[n + 1];
            float2 vA = make_float2(acc[i][j][0] + bv0, acc[i][j][1] + bv1);
            float2 vB = make_float2(acc[i][j][2] + bv0, acc[i][j][3] + bv1);
            *reinterpret_cast<float2*>(rowA + n) = vA;
            *reinterpret_cast<float2*>(rowB + n) = vB;
        }
    }
}

// ---------------- host launcher ----------------
extern "C" void kernel_launch(void* const* d_in, const int* in_sizes, int n_in,
                              void* d_out, int out_size) {
    const int*   tgt    = (const int*)  d_in[0];
    const float* enc    = (const float*)d_in[1];
    const float* hidden = (const float*)d_in[2];
    const float* cell   = (const float*)d_in[3];
    const float* emb    = (const float*)d_in[4];
    const float* W_a    = (const float*)d_in[5];
    const float* W_ih0  = (const float*)d_in[6];
    const float* W_hh0  = (const float*)d_in[7];
    const float* b_ih0  = (const float*)d_in[8];
    const float* b_hh0  = (const float*)d_in[9];
    const float* W_ih1  = (const float*)d_in[10];
    const float* W_hh1  = (const float*)d_in[11];
    const float* b_ih1  = (const float*)d_in[12];
    const float* b_hh1  = (const float*)d_in[13];
    const float* W_out  = (const float*)d_in[14];
    const float* b_out  = (const float*)d_in[15];
    float* out = (float*)d_out;

    float *p_feat, *p_embF, *p_encproj, *p_encIHC, *p_embpre;
    __nv_bfloat16 *p_WH, *p_WL, *p_fH, *p_fL;
    cudaGetSymbolAddress((void**)&p_feat,    g_feat);
    cudaGetSymbolAddress((void**)&p_embF,    g_embF);
    cudaGetSymbolAddress((void**)&p_encproj, g_encproj);
    cudaGetSymbolAddress((void**)&p_encIHC,  g_encIHC);
    cudaGetSymbolAddress((void**)&p_embpre,  g_embpre);
    cudaGetSymbolAddress((void**)&p_WH,      g_WH);
    cudaGetSymbolAddress((void**)&p_WL,      g_WL);
    cudaGetSymbolAddress((void**)&p_fH,      g_fH);
    cudaGetSymbolAddress((void**)&p_fL,      g_fL);

    init_state_kernel<<<64, 512>>>(hidden, cell);
    embed_kernel<<<BATCH * TT, 128>>>(tgt, emb);

    // fp32 prep GEMMs
    // encproj[r, j] = sum_k enc[r,k] * W_a[k, j]        (NN: enc @ W_a)
    gemm64_nn_f32<<<dim3(8, 32), 256>>>(enc, W_a, 512, p_encproj, 512);
    // embpre[r, n] = sum_k embF[r,k] * W_ih0[n, k]      (NT)
    gemm64_nt_f32<<<dim3(32, 32), 256>>>(p_embF, W_ih0, 1024, p_embpre, 2048);
    // encIHC[r, n] = sum_k enc[r,k] * W_ih0[n, 512+k]   (NT)
    gemm64_nt_f32<<<dim3(32, 32), 256>>>(enc, W_ih0 + 512, 1024, p_encIHC, 2048);

    // fused persistent recurrence (fp32, 4 barriers/step, 128 CTAs)
    cudaFuncSetAttribute(decoder_persistent,
                         cudaFuncAttributeMaxDynamicSharedMemorySize, DSM_BYTES);
    decoder_persistent<<<NCTA, 256, DSM_BYTES>>>(enc, W_hh0, W_hh1, W_ih1,
                                                 b_ih0, b_hh0, b_ih1, b_hh1);

    // split W_out and feat for big GEMM
    split_bf16_kernel<<<4096, 256>>>((const float4*)W_out, (uint2*)p_WH, (uint2*)p_WL,
                                     VV * 1024 / 4);
    split_bf16_kernel<<<2048, 256>>>((const float4*)p_feat, (uint2*)p_fH, (uint2*)p_fL,
                                     2048 * 1024 / 4);

    // tensor-core projection
    cudaFuncSetAttribute(big_gemm_mma, cudaFuncAttributeMaxDynamicSharedMemorySize, GEMM_SMEM);
    big_gemm_mma<<<dim3(16, VV / 128), 256, GEMM_SMEM>>>(p_fH, p_fL, p_WH, p_WL, b_out, out);

    tail_copy_kernel<<<64, 512>>>(out);
}